// round 4
// baseline (speedup 1.0000x reference)
#include <cuda_runtime.h>
#include <cuda_fp16.h>
#include <math.h>

#define NN 100000
#define EE 3200000
#define BB 1000
#define FIN 128
#define SF 12         // fp32 row stride (p, q, g)
#define SH 16         // fp16 row stride (messages): 32B

#define SCAN_CHUNK 1024
#define SCAN_BLOCKS 98          // 98*1024 = 100352 >= NN+1

// Scratch (static device globals)
__device__ float  g_p   [NN * SF];   // x @ W1[0:128]             (fp32)
__device__ __half g_y   [NN * SH];   // x @ W1[128:256]           (fp16 msg layer1)
__device__ float  g_q   [NN * SF];   // h @ W2[0:10]              (fp32)
__device__ __half g_z   [NN * SH];   // h @ W2[10:20]             (fp16 msg layer2)
__device__ float  g_g   [BB * SF];   // pooled h2, slot10 = node count
__device__ int    g_deg [NN + 1];    // in-degree histogram
__device__ int    g_ptrx[NN + 1];    // exclusive row pointers
__device__ int    g_cur [NN + 1];    // fill cursors
__device__ int    g_part[SCAN_BLOCKS];
__device__ int    g_perm[EE];        // src ids grouped by dst

__device__ __forceinline__ void red_add_v4_f32(float* p, float a, float b, float c, float d) {
    asm volatile("red.global.add.v4.f32 [%0], {%1,%2,%3,%4};"
                 :: "l"(p), "f"(a), "f"(b), "f"(c), "f"(d) : "memory");
}
__device__ __forceinline__ unsigned pack_h2(float lo, float hi) {
    __half2 h = __floats2half2_rn(lo, hi);
    return *(unsigned*)&h;
}
__device__ __forceinline__ unsigned long long pack_f32x2(float lo, float hi) {
    unsigned long long r;
    asm("mov.b64 %0, {%1,%2};" : "=l"(r) : "f"(lo), "f"(hi));
    return r;
}
__device__ __forceinline__ void unpack_f32x2(float& lo, float& hi, unsigned long long v) {
    asm("mov.b64 {%0,%1}, %2;" : "=f"(lo), "=f"(hi) : "l"(v));
}
__device__ __forceinline__ void fma_f32x2(unsigned long long& acc,
                                          unsigned long long a, unsigned long long b) {
    asm("fma.rn.f32x2 %0, %1, %2, %0;" : "+l"(acc) : "l"(a), "l"(b));
}

// ---------------------------------------------------------------------------
// K1: p = x @ W1[0:128,:] (fp32), y = x @ W1[128:256,:] (fp16), f32x2 FMAs
// ---------------------------------------------------------------------------
__global__ void k1_project(const float* __restrict__ x, const float* __restrict__ W1) {
    __shared__ __align__(16) float sW[2 * FIN * 10];
    for (int i = threadIdx.x; i < 2 * FIN * 10; i += blockDim.x) sW[i] = W1[i];
    __syncthreads();

    int n = blockIdx.x * blockDim.x + threadIdx.x;
    if (n >= NN) return;

    unsigned long long accP[5], accY[5];
#pragma unroll
    for (int j = 0; j < 5; j++) { accP[j] = 0ull; accY[j] = 0ull; }

    const float4* xr = (const float4*)(x + (size_t)n * FIN);
#pragma unroll 4
    for (int f4 = 0; f4 < FIN / 4; f4++) {
        float4 xv = xr[f4];
        float xf[4] = {xv.x, xv.y, xv.z, xv.w};
#pragma unroll
        for (int k = 0; k < 4; k++) {
            int f = f4 * 4 + k;
            unsigned long long bx = pack_f32x2(xf[k], xf[k]);
            const unsigned long long* wp = (const unsigned long long*)&sW[f * 10];
            const unsigned long long* wy = (const unsigned long long*)&sW[(FIN + f) * 10];
#pragma unroll
            for (int j = 0; j < 5; j++) {
                fma_f32x2(accP[j], bx, wp[j]);
                fma_f32x2(accY[j], bx, wy[j]);
            }
        }
    }

    float* pr = g_p + (size_t)n * SF;
    float yv[10];
#pragma unroll
    for (int j = 0; j < 5; j++) {
        float lo, hi;
        unpack_f32x2(lo, hi, accP[j]);
        pr[2 * j] = lo; pr[2 * j + 1] = hi;
        unpack_f32x2(yv[2 * j], yv[2 * j + 1], accY[j]);
    }

    uint4 u0, u1;
    u0.x = pack_h2(yv[0], yv[1]);
    u0.y = pack_h2(yv[2], yv[3]);
    u0.z = pack_h2(yv[4], yv[5]);
    u0.w = pack_h2(yv[6], yv[7]);
    u1.x = pack_h2(yv[8], yv[9]);
    u1.y = 0; u1.z = 0; u1.w = 0;
    uint4* yr = (uint4*)(g_y + (size_t)n * SH);
    yr[0] = u0; yr[1] = u1;
}

// ---------------------------------------------------------------------------
// CSR build
// ---------------------------------------------------------------------------
__global__ void k_hist(const int* __restrict__ dst) {
    int e = blockIdx.x * blockDim.x + threadIdx.x;
    if (e < EE) atomicAdd(&g_deg[dst[e]], 1);
}

__global__ void k_scan1() {   // per-chunk sums -> g_part
    __shared__ int sm[256];
    int base = blockIdx.x * SCAN_CHUNK;
    int sum = 0;
    for (int i = threadIdx.x; i < SCAN_CHUNK; i += 256) {
        int idx = base + i;
        sum += (idx <= NN) ? g_deg[idx] : 0;
    }
    sm[threadIdx.x] = sum;
    __syncthreads();
    for (int o = 128; o > 0; o >>= 1) {
        if (threadIdx.x < o) sm[threadIdx.x] += sm[threadIdx.x + o];
        __syncthreads();
    }
    if (threadIdx.x == 0) g_part[blockIdx.x] = sm[0];
}

__global__ void k_scan2() {   // serial exclusive scan of 98 partials
    if (threadIdx.x == 0) {
        int run = 0;
        for (int i = 0; i < SCAN_BLOCKS; i++) {
            int v = g_part[i];
            g_part[i] = run;
            run += v;
        }
    }
}

__global__ void k_scan3() {   // chunk-local exclusive scan + partial offset
    __shared__ int sm[SCAN_CHUNK];
    int gid = blockIdx.x * SCAN_CHUNK + threadIdx.x;
    int v = (gid <= NN) ? g_deg[gid] : 0;
    sm[threadIdx.x] = v;
    __syncthreads();
#pragma unroll
    for (int off = 1; off < SCAN_CHUNK; off <<= 1) {
        int t = sm[threadIdx.x];
        if (threadIdx.x >= off) t += sm[threadIdx.x - off];
        __syncthreads();
        sm[threadIdx.x] = t;
        __syncthreads();
    }
    if (gid <= NN) {
        int excl = g_part[blockIdx.x] + (threadIdx.x > 0 ? sm[threadIdx.x - 1] : 0);
        g_ptrx[gid] = excl;
        g_cur[gid] = excl;
    }
}

__global__ void k_perm(const int* __restrict__ src, const int* __restrict__ dst) {
    int e = blockIdx.x * blockDim.x + threadIdx.x;
    if (e >= EE) return;
    int pos = atomicAdd(&g_cur[dst[e]], 1);
    g_perm[pos] = src[e];
}

// ---------------------------------------------------------------------------
// AGG1: warp per node: mean of y[neighbors] (fp32 acc), fuse relu + layer2 GEMM
// ---------------------------------------------------------------------------
__global__ void k_agg1(const float* __restrict__ W2) {
    __shared__ float sW[200];
    for (int i = threadIdx.x; i < 200; i += blockDim.x) sW[i] = W2[i];
    __syncthreads();

    int warp = threadIdx.x >> 5;
    int lane = threadIdx.x & 31;
    int n = blockIdx.x * (blockDim.x >> 5) + warp;
    if (n >= NN) return;

    int beg = __shfl_sync(0xffffffff, lane == 0 ? g_ptrx[n] : 0, 0);
    int end = __shfl_sync(0xffffffff, lane == 0 ? g_ptrx[n + 1] : 0, 0);

    float acc[10];
#pragma unroll
    for (int j = 0; j < 10; j++) acc[j] = 0.f;

    for (int i = beg + lane; i < end; i += 32) {
        int s = g_perm[i];
        const uint4* row = (const uint4*)(g_y + (size_t)s * SH);
        uint4 a = row[0];
        unsigned b0 = ((const unsigned*)row)[4];   // slots 8,9
        float2 t;
        t = __half22float2(*(__half2*)&a.x); acc[0] += t.x; acc[1] += t.y;
        t = __half22float2(*(__half2*)&a.y); acc[2] += t.x; acc[3] += t.y;
        t = __half22float2(*(__half2*)&a.z); acc[4] += t.x; acc[5] += t.y;
        t = __half22float2(*(__half2*)&a.w); acc[6] += t.x; acc[7] += t.y;
        t = __half22float2(*(__half2*)&b0);  acc[8] += t.x; acc[9] += t.y;
    }
    __syncwarp();
#pragma unroll
    for (int j = 0; j < 10; j++)
        for (int o = 16; o > 0; o >>= 1)
            acc[j] += __shfl_down_sync(0xffffffff, acc[j], o);

    if (lane == 0) {
        float inv = 1.f / fmaxf((float)(end - beg), 1.f);
        const float* pr = g_p + (size_t)n * SF;
        float h[10];
#pragma unroll
        for (int j = 0; j < 10; j++)
            h[j] = fmaxf(pr[j] + acc[j] * inv, 0.f);

        float q[10], z[10];
#pragma unroll
        for (int j = 0; j < 10; j++) { q[j] = 0.f; z[j] = 0.f; }
#pragma unroll
        for (int k = 0; k < 10; k++) {
#pragma unroll
            for (int j = 0; j < 10; j++) {
                q[j] += h[k] * sW[k * 10 + j];
                z[j] += h[k] * sW[(10 + k) * 10 + j];
            }
        }
        float* qr = g_q + (size_t)n * SF;
#pragma unroll
        for (int j = 0; j < 10; j++) qr[j] = q[j];

        uint4 u0, u1;
        u0.x = pack_h2(z[0], z[1]);
        u0.y = pack_h2(z[2], z[3]);
        u0.z = pack_h2(z[4], z[5]);
        u0.w = pack_h2(z[6], z[7]);
        u1.x = pack_h2(z[8], z[9]);
        u1.y = 0; u1.z = 0; u1.w = 0;
        uint4* zr = (uint4*)(g_z + (size_t)n * SH);
        zr[0] = u0; zr[1] = u1;
    }
}

// ---------------------------------------------------------------------------
// AGG2: warp per node: mean of z[neighbors], fuse h2 + graph pool RED
// ---------------------------------------------------------------------------
__global__ void k_agg2(const int* __restrict__ batch) {
    int warp = threadIdx.x >> 5;
    int lane = threadIdx.x & 31;
    int n = blockIdx.x * (blockDim.x >> 5) + warp;
    if (n >= NN) return;

    int beg = __shfl_sync(0xffffffff, lane == 0 ? g_ptrx[n] : 0, 0);
    int end = __shfl_sync(0xffffffff, lane == 0 ? g_ptrx[n + 1] : 0, 0);

    float acc[10];
#pragma unroll
    for (int j = 0; j < 10; j++) acc[j] = 0.f;

    for (int i = beg + lane; i < end; i += 32) {
        int s = g_perm[i];
        const uint4* row = (const uint4*)(g_z + (size_t)s * SH);
        uint4 a = row[0];
        unsigned b0 = ((const unsigned*)row)[4];
        float2 t;
        t = __half22float2(*(__half2*)&a.x); acc[0] += t.x; acc[1] += t.y;
        t = __half22float2(*(__half2*)&a.y); acc[2] += t.x; acc[3] += t.y;
        t = __half22float2(*(__half2*)&a.z); acc[4] += t.x; acc[5] += t.y;
        t = __half22float2(*(__half2*)&a.w); acc[6] += t.x; acc[7] += t.y;
        t = __half22float2(*(__half2*)&b0);  acc[8] += t.x; acc[9] += t.y;
    }
    __syncwarp();
#pragma unroll
    for (int j = 0; j < 10; j++)
        for (int o = 16; o > 0; o >>= 1)
            acc[j] += __shfl_down_sync(0xffffffff, acc[j], o);

    if (lane == 0) {
        float inv = 1.f / fmaxf((float)(end - beg), 1.f);
        const float* qr = g_q + (size_t)n * SF;
        float h2[10];
#pragma unroll
        for (int j = 0; j < 10; j++) h2[j] = qr[j] + acc[j] * inv;

        float* o = g_g + (size_t)batch[n] * SF;
        red_add_v4_f32(o + 0, h2[0], h2[1], h2[2], h2[3]);
        red_add_v4_f32(o + 4, h2[4], h2[5], h2[6], h2[7]);
        red_add_v4_f32(o + 8, h2[8], h2[9], 1.0f,  0.0f);
    }
}

// ---------------------------------------------------------------------------
// K6: out[b] = sigmoid( (sum_g / cnt) . Wfc )
// ---------------------------------------------------------------------------
__global__ void k6_head(const float* __restrict__ Wfc, float* __restrict__ out) {
    int b = blockIdx.x * blockDim.x + threadIdx.x;
    if (b >= BB) return;
    const float* gr = g_g + (size_t)b * SF;
    float inv = 1.f / fmaxf(gr[10], 1.f);
    float v = 0.f;
#pragma unroll
    for (int j = 0; j < 10; j++) v += gr[j] * Wfc[j];
    v *= inv;
    out[b] = 1.f / (1.f + expf(-v));
}

// ---------------------------------------------------------------------------
extern "C" void kernel_launch(void* const* d_in, const int* in_sizes, int n_in,
                              void* d_out, int out_size) {
    const float* x     = (const float*)d_in[0];
    const int*   ei    = (const int*)  d_in[1];   // src = ei[0:E), dst = ei[E:2E)
    const int*   batch = (const int*)  d_in[2];
    const float* W1    = (const float*)d_in[3];
    const float* W2    = (const float*)d_in[4];
    const float* Wfc   = (const float*)d_in[5];
    float*       out   = (float*)d_out;

    void *p_deg, *p_g;
    cudaGetSymbolAddress(&p_deg, g_deg);
    cudaGetSymbolAddress(&p_g,   g_g);
    cudaMemsetAsync(p_deg, 0, (NN + 1) * sizeof(int));
    cudaMemsetAsync(p_g,   0, (size_t)BB * SF * sizeof(float));

    const int T = 256;
    k1_project<<<(NN + T - 1) / T, T>>>(x, W1);
    k_hist    <<<(EE + T - 1) / T, T>>>(ei + EE);
    k_scan1   <<<SCAN_BLOCKS, 256>>>();
    k_scan2   <<<1, 32>>>();
    k_scan3   <<<SCAN_BLOCKS, SCAN_CHUNK>>>();
    k_perm    <<<(EE + T - 1) / T, T>>>(ei, ei + EE);
    k_agg1    <<<(NN * 32 + T - 1) / T, T>>>(W2);
    k_agg2    <<<(NN * 32 + T - 1) / T, T>>>(batch);
    k6_head   <<<(BB + T - 1) / T, T>>>(Wfc, out);
}

// round 5
// speedup vs baseline: 1.7731x; 1.7731x over previous
#include <cuda_runtime.h>
#include <cuda_fp16.h>
#include <math.h>

#define NN 100000
#define EE 3200000
#define BB 1000
#define FIN 128
#define SF 12         // fp32 row stride (p, q, g): 10 data + count + pad
#define SH 16         // fp16 row stride (messages/accumulators): 32B = 1 sector

// Scratch (static device globals: no allocation anywhere)
__device__ float  g_p [NN * SF];   // x @ W1[0:128]               (fp32)
__device__ __half g_y [NN * SH];   // x @ W1[128:256], slot10=1.0 (fp16 message)
__device__ __half g_s1[NN * SH];   // edge-accumulated y          (fp16 accumulator)
__device__ float  g_q [NN * SF];   // h @ W2[0:10]                (fp32)
__device__ __half g_z [NN * SH];   // h @ W2[10:20], slot10=1.0   (fp16 message)
__device__ __half g_s2[NN * SH];   // edge-accumulated z          (fp16 accumulator)
__device__ float  g_g [BB * SF];   // pooled h2 per graph, slot10 = node count

__device__ __forceinline__ void red_add_v4_f32(float* p, float a, float b, float c, float d) {
    asm volatile("red.global.add.v4.f32 [%0], {%1,%2,%3,%4};"
                 :: "l"(p), "f"(a), "f"(b), "f"(c), "f"(d) : "memory");
}
__device__ __forceinline__ void red_add_v4_h2(void* p, unsigned a, unsigned b, unsigned c, unsigned d) {
    asm volatile("red.global.add.noftz.v4.f16x2 [%0], {%1,%2,%3,%4};"
                 :: "l"(p), "r"(a), "r"(b), "r"(c), "r"(d) : "memory");
}
__device__ __forceinline__ void red_add_v2_h2(void* p, unsigned a, unsigned b) {
    asm volatile("red.global.add.noftz.v2.f16x2 [%0], {%1,%2};"
                 :: "l"(p), "r"(a), "r"(b) : "memory");
}

__device__ __forceinline__ unsigned pack_h2(float lo, float hi) {
    __half2 h = __floats2half2_rn(lo, hi);
    return *(unsigned*)&h;
}
__device__ __forceinline__ unsigned long long pack_f32x2(float lo, float hi) {
    unsigned long long r;
    asm("mov.b64 %0, {%1,%2};" : "=l"(r) : "f"(lo), "f"(hi));
    return r;
}
__device__ __forceinline__ void unpack_f32x2(float& lo, float& hi, unsigned long long v) {
    asm("mov.b64 {%0,%1}, %2;" : "=f"(lo), "=f"(hi) : "l"(v));
}
__device__ __forceinline__ void fma_f32x2(unsigned long long& acc,
                                          unsigned long long a, unsigned long long b) {
    asm("fma.rn.f32x2 %0, %1, %2, %0;" : "+l"(acc) : "l"(a), "l"(b));
}

// ---------------------------------------------------------------------------
// K1: p = x @ W1[0:128,:] (fp32), y = x @ W1[128:256,:] (fp16, slot10=1.0)
//     Also zeroes this node's g_s1 row (replaces a memset pass).
// ---------------------------------------------------------------------------
__global__ void k1_project(const float* __restrict__ x, const float* __restrict__ W1) {
    __shared__ __align__(16) float sW[2 * FIN * 10];   // 10 KB
    for (int i = threadIdx.x; i < 2 * FIN * 10; i += blockDim.x) sW[i] = W1[i];
    __syncthreads();

    int n = blockIdx.x * blockDim.x + threadIdx.x;
    if (n >= NN) return;

    // zero accumulator row for the upcoming scatter
    uint4 zz = {0, 0, 0, 0};
    uint4* s1r = (uint4*)(g_s1 + (size_t)n * SH);
    s1r[0] = zz; s1r[1] = zz;

    unsigned long long accP[5], accY[5];
#pragma unroll
    for (int j = 0; j < 5; j++) { accP[j] = 0ull; accY[j] = 0ull; }

    const float4* xr = (const float4*)(x + (size_t)n * FIN);
#pragma unroll 4
    for (int f4 = 0; f4 < FIN / 4; f4++) {
        float4 xv = xr[f4];
        float xf[4] = {xv.x, xv.y, xv.z, xv.w};
#pragma unroll
        for (int k = 0; k < 4; k++) {
            int f = f4 * 4 + k;
            unsigned long long bx = pack_f32x2(xf[k], xf[k]);
            const unsigned long long* wp = (const unsigned long long*)&sW[f * 10];
            const unsigned long long* wy = (const unsigned long long*)&sW[(FIN + f) * 10];
#pragma unroll
            for (int j = 0; j < 5; j++) {
                fma_f32x2(accP[j], bx, wp[j]);
                fma_f32x2(accY[j], bx, wy[j]);
            }
        }
    }

    float* pr = g_p + (size_t)n * SF;
    float yv[10];
#pragma unroll
    for (int j = 0; j < 5; j++) {
        float lo, hi;
        unpack_f32x2(lo, hi, accP[j]);
        pr[2 * j] = lo; pr[2 * j + 1] = hi;
        unpack_f32x2(yv[2 * j], yv[2 * j + 1], accY[j]);
    }

    uint4 u0, u1;
    u0.x = pack_h2(yv[0], yv[1]);
    u0.y = pack_h2(yv[2], yv[3]);
    u0.z = pack_h2(yv[4], yv[5]);
    u0.w = pack_h2(yv[6], yv[7]);
    u1.x = pack_h2(yv[8], yv[9]);
    u1.y = pack_h2(1.0f, 0.0f);     // degree carrier
    u1.z = 0; u1.w = 0;
    uint4* yr = (uint4*)(g_y + (size_t)n * SH);
    yr[0] = u0; yr[1] = u1;
}

// ---------------------------------------------------------------------------
// K2/K4: edge scatter fp16, 4 edges per thread with int4 index loads.
// acc[dst] += msg[src]  (24B via v4.f16x2 + v2.f16x2; 2 LTS ops/edge)
// Grid exactly covers EE/4 threads — no tail.
// ---------------------------------------------------------------------------
__global__ void k_edge_scatter(const int* __restrict__ src, const int* __restrict__ dst,
                               const __half* __restrict__ msg, __half* __restrict__ acc) {
    int t = blockIdx.x * blockDim.x + threadIdx.x;   // t in [0, EE/4)
    int4 s4 = ((const int4*)src)[t];
    int4 d4 = ((const int4*)dst)[t];
    int ss[4] = {s4.x, s4.y, s4.z, s4.w};
    int dd[4] = {d4.x, d4.y, d4.z, d4.w};

    uint4 a[4]; uint2 b[4];
#pragma unroll
    for (int k = 0; k < 4; k++) {
        const uint4* v = (const uint4*)(msg + (size_t)ss[k] * SH);
        a[k] = v[0];
        b[k] = ((const uint2*)v)[2];
    }
#pragma unroll
    for (int k = 0; k < 4; k++) {
        __half* o = acc + (size_t)dd[k] * SH;
        red_add_v4_h2(o,     a[k].x, a[k].y, a[k].z, a[k].w);
        red_add_v2_h2(o + 8, b[k].x, b[k].y);
    }
}

// ---------------------------------------------------------------------------
// K3: h = relu(p + s1/deg); q = h @ W2[0:10,:] (fp32), z = h @ W2[10:20,:] (fp16)
//     Also zeroes g_s2 row and (for n < BB) g_g row — replaces two memsets.
// ---------------------------------------------------------------------------
__global__ void k3_layer2in(const float* __restrict__ W2) {
    __shared__ float sW[200];
    for (int i = threadIdx.x; i < 200; i += blockDim.x) sW[i] = W2[i];
    __syncthreads();

    int n = blockIdx.x * blockDim.x + threadIdx.x;
    if (n >= NN) return;

    // zero next-layer scatter accumulator + pool accumulator
    uint4 zz = {0, 0, 0, 0};
    uint4* s2r = (uint4*)(g_s2 + (size_t)n * SH);
    s2r[0] = zz; s2r[1] = zz;
    if (n < BB) {
        float* gg = g_g + (size_t)n * SF;
#pragma unroll
        for (int j = 0; j < SF; j++) gg[j] = 0.f;
    }

    const float* pr = g_p + (size_t)n * SF;
    const uint4* sv = (const uint4*)(g_s1 + (size_t)n * SH);
    uint4 a = sv[0];
    uint2 b = ((const uint2*)sv)[2];

    float s[12];
    {
        float2 t;
        t = __half22float2(*(__half2*)&a.x); s[0] = t.x; s[1] = t.y;
        t = __half22float2(*(__half2*)&a.y); s[2] = t.x; s[3] = t.y;
        t = __half22float2(*(__half2*)&a.z); s[4] = t.x; s[5] = t.y;
        t = __half22float2(*(__half2*)&a.w); s[6] = t.x; s[7] = t.y;
        t = __half22float2(*(__half2*)&b.x); s[8] = t.x; s[9] = t.y;
        t = __half22float2(*(__half2*)&b.y); s[10] = t.x; s[11] = t.y;
    }
    float inv = 1.f / fmaxf(s[10], 1.f);

    float h[10];
#pragma unroll
    for (int j = 0; j < 10; j++)
        h[j] = fmaxf(pr[j] + s[j] * inv, 0.f);

    float q[10], z[10];
#pragma unroll
    for (int j = 0; j < 10; j++) { q[j] = 0.f; z[j] = 0.f; }
#pragma unroll
    for (int k = 0; k < 10; k++) {
        const float* wq = &sW[k * 10];
        const float* wz = &sW[(10 + k) * 10];
#pragma unroll
        for (int j = 0; j < 10; j++) {
            q[j] += h[k] * wq[j];
            z[j] += h[k] * wz[j];
        }
    }

    float* qr = g_q + (size_t)n * SF;
#pragma unroll
    for (int j = 0; j < 10; j++) qr[j] = q[j];

    uint4 u0, u1;
    u0.x = pack_h2(z[0], z[1]);
    u0.y = pack_h2(z[2], z[3]);
    u0.z = pack_h2(z[4], z[5]);
    u0.w = pack_h2(z[6], z[7]);
    u1.x = pack_h2(z[8], z[9]);
    u1.y = pack_h2(1.0f, 0.0f);
    u1.z = 0; u1.w = 0;
    uint4* zr = (uint4*)(g_z + (size_t)n * SH);
    zr[0] = u0; zr[1] = u1;
}

// ---------------------------------------------------------------------------
// K5: h2 = q + s2/deg; pool (fp32 REDs) into g[batch[n]] (slot10 = node count)
// ---------------------------------------------------------------------------
__global__ void k5_pool(const int* __restrict__ batch) {
    int n = blockIdx.x * blockDim.x + threadIdx.x;
    if (n >= NN) return;

    const float* qr = g_q + (size_t)n * SF;
    const uint4* sv = (const uint4*)(g_s2 + (size_t)n * SH);
    uint4 a = sv[0];
    uint2 b = ((const uint2*)sv)[2];

    float s[12];
    {
        float2 t;
        t = __half22float2(*(__half2*)&a.x); s[0] = t.x; s[1] = t.y;
        t = __half22float2(*(__half2*)&a.y); s[2] = t.x; s[3] = t.y;
        t = __half22float2(*(__half2*)&a.z); s[4] = t.x; s[5] = t.y;
        t = __half22float2(*(__half2*)&a.w); s[6] = t.x; s[7] = t.y;
        t = __half22float2(*(__half2*)&b.x); s[8] = t.x; s[9] = t.y;
        t = __half22float2(*(__half2*)&b.y); s[10] = t.x; s[11] = t.y;
    }
    float inv = 1.f / fmaxf(s[10], 1.f);

    float h2[12];
#pragma unroll
    for (int j = 0; j < 10; j++) h2[j] = qr[j] + s[j] * inv;
    h2[10] = 1.f; h2[11] = 0.f;

    int bg = batch[n];
    float* o = g_g + (size_t)bg * SF;
    red_add_v4_f32(o + 0, h2[0], h2[1], h2[2],  h2[3]);
    red_add_v4_f32(o + 4, h2[4], h2[5], h2[6],  h2[7]);
    red_add_v4_f32(o + 8, h2[8], h2[9], h2[10], h2[11]);
}

// ---------------------------------------------------------------------------
// K6: out[b] = sigmoid( (sum_g / cnt) . Wfc )
// ---------------------------------------------------------------------------
__global__ void k6_head(const float* __restrict__ Wfc, float* __restrict__ out) {
    int b = blockIdx.x * blockDim.x + threadIdx.x;
    if (b >= BB) return;
    const float* gr = g_g + (size_t)b * SF;
    float inv = 1.f / fmaxf(gr[10], 1.f);
    float v = 0.f;
#pragma unroll
    for (int j = 0; j < 10; j++) v += gr[j] * Wfc[j];
    v *= inv;
    out[b] = 1.f / (1.f + expf(-v));
}

// ---------------------------------------------------------------------------
extern "C" void kernel_launch(void* const* d_in, const int* in_sizes, int n_in,
                              void* d_out, int out_size) {
    const float* x     = (const float*)d_in[0];
    const int*   ei    = (const int*)  d_in[1];   // src = ei[0:E), dst = ei[E:2E)
    const int*   batch = (const int*)  d_in[2];
    const float* W1    = (const float*)d_in[3];
    const float* W2    = (const float*)d_in[4];
    const float* Wfc   = (const float*)d_in[5];
    float*       out   = (float*)d_out;

    void *p_y, *p_z, *p_s1, *p_s2;
    cudaGetSymbolAddress(&p_y,  g_y);
    cudaGetSymbolAddress(&p_z,  g_z);
    cudaGetSymbolAddress(&p_s1, g_s1);
    cudaGetSymbolAddress(&p_s2, g_s2);

    const int T = 256;
    k1_project    <<<(NN + T - 1) / T, T>>>(x, W1);
    k_edge_scatter<<<EE / 4 / T, T>>>(ei, ei + EE, (const __half*)p_y, (__half*)p_s1);
    k3_layer2in   <<<(NN + T - 1) / T, T>>>(W2);
    k_edge_scatter<<<EE / 4 / T, T>>>(ei, ei + EE, (const __half*)p_z, (__half*)p_s2);
    k5_pool       <<<(NN + T - 1) / T, T>>>(batch);
    k6_head       <<<(BB + T - 1) / T, T>>>(Wfc, out);
}